// round 13
// baseline (speedup 1.0000x reference)
#include <cuda_runtime.h>
#include <cuda_bf16.h>

// z:     [M=4096, P=2]  float32
// mu:    [B=8, N=2048, P=2] float32
// sigma: [B=8, N=2048, 1] float32
// out:   [B, N, M] float32 = exp(-d2 / (2*sig^2)), sig = clip(sigma, 0.1, 10)
//
// Single kernel. 740 blocks; block b owns a CONTIGUOUS chunk of ~23 full rows,
// so each block emits one sequential ~360KB store stream (DRAM page locality),
// instead of 8KB bursts strided by ~6MB.
// Each thread owns 16 consecutive m-values; z (zx,zy only, 32 regs) loaded once.
// Per element: arg = zx*(c*zx+A) + zy*(c*zy+B) + D  -> 4 FFMA + 1 EX2.
// Per-row params computed inline (row owned by exactly one block), with mu/sigma
// prefetched one row ahead.

#define M_GRID  4096
#define THREADS 256
#define BLOCKS_PER_SM 5
#define NBLOCKS (148 * BLOCKS_PER_SM)   // 740
#define M_PER_THREAD 16

__device__ __forceinline__ float ex2_fast(float x) {
    float r;
    asm("ex2.approx.ftz.f32 %0, %1;" : "=f"(r) : "f"(x));
    return r;
}

__global__ void __launch_bounds__(THREADS, BLOCKS_PER_SM) rbf_kernel(
    const float* __restrict__ z,
    const float* __restrict__ mu,
    const float* __restrict__ sigma,
    float* __restrict__ out,
    int rows)
{
    const int t = threadIdx.x;

    // Contiguous row chunk for this block
    const int chunk  = (rows + NBLOCKS - 1) / NBLOCKS;
    const int rbegin = blockIdx.x * chunk;
    int rend = rbegin + chunk;
    if (rend > rows) rend = rows;
    if (rbegin >= rows) return;

    // This thread's 16 m-values: m0 = t*16. Load z once: 8 float4.
    const int m0 = t * M_PER_THREAD;
    float zx[M_PER_THREAD], zy[M_PER_THREAD];
    {
        const float4* zv = reinterpret_cast<const float4*>(z + 2 * m0);
        #pragma unroll
        for (int i = 0; i < 8; i++) {
            float4 v = zv[i];
            zx[2*i]   = v.x; zy[2*i]   = v.y;
            zx[2*i+1] = v.z; zy[2*i+1] = v.w;
        }
    }

    // Prefetch first row's raw params
    float pmu0 = __ldg(&mu[rbegin * 2 + 0]);
    float pmu1 = __ldg(&mu[rbegin * 2 + 1]);
    float psig = __ldg(&sigma[rbegin]);

    for (int row = rbegin; row < rend; row++) {
        const float mu0 = pmu0, mu1 = pmu1;
        float s = fminf(fmaxf(psig, 0.1f), 10.0f);

        // Prefetch next row (overlaps with compute/stores below)
        if (row + 1 < rend) {
            pmu0 = __ldg(&mu[(row + 1) * 2 + 0]);
            pmu1 = __ldg(&mu[(row + 1) * 2 + 1]);
            psig = __ldg(&sigma[row + 1]);
        }

        // c = -log2(e)/(2 s^2); A = -2c*mu0; B = -2c*mu1; D = c*(mu0^2+mu1^2)
        const float c = __fdividef(-1.44269504088896340736f, 2.0f * s * s);
        const float A = -2.0f * c * mu0;
        const float B = -2.0f * c * mu1;
        const float D = c * (mu0 * mu0 + mu1 * mu1);

        float4* ov = reinterpret_cast<float4*>(out + (size_t)row * M_GRID + m0);
        #pragma unroll
        for (int g = 0; g < 4; g++) {
            float4 o;
            float e;
            e = fmaf(zx[4*g+0], fmaf(zx[4*g+0], c, A),
                fmaf(zy[4*g+0], fmaf(zy[4*g+0], c, B), D)); o.x = ex2_fast(e);
            e = fmaf(zx[4*g+1], fmaf(zx[4*g+1], c, A),
                fmaf(zy[4*g+1], fmaf(zy[4*g+1], c, B), D)); o.y = ex2_fast(e);
            e = fmaf(zx[4*g+2], fmaf(zx[4*g+2], c, A),
                fmaf(zy[4*g+2], fmaf(zy[4*g+2], c, B), D)); o.z = ex2_fast(e);
            e = fmaf(zx[4*g+3], fmaf(zx[4*g+3], c, A),
                fmaf(zy[4*g+3], fmaf(zy[4*g+3], c, B), D)); o.w = ex2_fast(e);
            __stcs(&ov[g], o);
        }
    }
}

extern "C" void kernel_launch(void* const* d_in, const int* in_sizes, int n_in,
                              void* d_out, int out_size)
{
    const float* z     = (const float*)d_in[0];  // [4096, 2]
    const float* mu    = (const float*)d_in[1];  // [8, 2048, 2]
    const float* sigma = (const float*)d_in[2];  // [8, 2048, 1]
    float* out = (float*)d_out;                  // [8, 2048, 4096]

    const int rows = in_sizes[2];                // B*N = 16384
    rbf_kernel<<<NBLOCKS, THREADS>>>(z, mu, sigma, out, rows);
}